// round 1
// baseline (speedup 1.0000x reference)
#include <cuda_runtime.h>

// Problem constants (match reference)
#define FEAT_W   32
#define FEAT_H   32
#define HW       1024          // 32*32
#define N_BOX    1024          // N
#define M_GT     64            // M
#define GT_STRIDE 14

// Output tensor offsets in floats (concatenation of the 12 returned tensors)
// BN = 4*1024 = 4096 ; per-channel slab = BN*HW = 4,194,304 floats
#define SLAB     4194304ll
#define OFF_CLS   (0ll)              // cls_label      (B,N,1,H,W)
#define OFF_CLSW  (SLAB*1)           // cls_label_w    (B,N,1,H,W)
#define OFF_R2    (SLAB*2)           // reg_2d         (B,N,2,H,W)
#define OFF_R2W   (SLAB*4)           // reg_2d_w       (B,N,2,H,W)
#define OFF_R3    (SLAB*6)           // reg_3d         (B,N,2,H,W)
#define OFF_R3W   (SLAB*8)           // reg_3d_w       (B,N,2,H,W)
#define OFF_DL    (SLAB*10)          // depth_label    (B,N,1,H,W)
#define OFF_DLW   (SLAB*11)          // depth_label_w  (B,N,1,H,W)
#define OFF_DIM   (SLAB*12)          // dim_label      (B,N,3,H,W)
#define OFF_DIMW  (SLAB*15)          // dim_label_w    (B,N,3,H,W)
#define OFF_ROT   (SLAB*18)          // rot_label      (B,N,1,H,W)
#define OFF_ROTW  (SLAB*19)          // rot_label_w    (B,N,1,H,W)

__device__ __forceinline__ void stream4(float* p, float a, float b, float c, float d) {
    float4 v = make_float4(a, b, c, d);
    __stcs(reinterpret_cast<float4*>(p), v);
}

__global__ __launch_bounds__(256, 8)
void rcnn3d_label_kernel(const float* __restrict__ boxes,
                         const float* __restrict__ gt_boxes,
                         const int*   __restrict__ match_pos_flag,
                         const int*   __restrict__ match_gt_id,
                         float*       __restrict__ out)
{
    const int bn  = blockIdx.x;            // 0 .. 4095  (b*N + n)
    const int b   = bn >> 10;              // N = 1024
    const int tid = threadIdx.x;           // 0 .. 255, one float4 of pixels each

    // ---- per-box scalars (uniform across block; broadcast loads from L1) ----
    const float x1 = __ldg(boxes + (size_t)bn * 4 + 0);
    const float y1 = __ldg(boxes + (size_t)bn * 4 + 1);
    const float x2 = __ldg(boxes + (size_t)bn * 4 + 2);
    const float y2 = __ldg(boxes + (size_t)bn * 4 + 3);

    const int gid  = __ldg(match_gt_id + bn);
    const int flag = __ldg(match_pos_flag + bn);

    const float* g = gt_boxes + ((size_t)b * M_GT + gid) * GT_STRIDE;
    const float kxg   = __ldg(g + 4);
    const float kyg   = __ldg(g + 5);
    const float vis   = __ldg(g + 6);
    const float dim0  = __ldg(g + 7);
    const float dim1  = __ldg(g + 8);
    const float dim2  = __ldg(g + 9);
    const float depth = __ldg(g + 12);
    const float rot   = __ldg(g + 13);

    const float cx = 0.5f * (x1 + x2);
    const float cy = 0.5f * (y1 + y2);
    const float hw = 0.5f * (x2 - x1) * 1.2f;   // EXPAND
    const float hh = 0.5f * (y2 - y1) * 1.2f;
    const float ex1 = cx - hw, ex2 = cx + hw;
    const float ey1 = cy - hh, ey2 = cy + hh;
    const float sx = (float)FEAT_W / (ex2 - ex1 + 1.0f);
    const float sy = (float)FEAT_H / (ey2 - ey1 + 1.0f);
    const float kx = (kxg - ex1) * sx;
    const float ky = (kyg - ey1) * sy;

    const bool valid = (vis != 0.0f) && (flag > 0);

    // ---- analytic 'has' : max score occurs at grid cell nearest (kx,ky) ----
    // score = exp(-((gx+0.5-kx)^2 + (gy+0.5-ky)^2)/5.12); monotone in dist^2,
    // separable => min over clamped-nearest integer per axis is the global max.
    int ixn = __float2int_rn(kx - 0.5f); ixn = min(FEAT_W - 1, max(0, ixn));
    int iyn = __float2int_rn(ky - 0.5f); iyn = min(FEAT_H - 1, max(0, iyn));
    {
        // (computed with identical float ops to the per-pixel path)
    }
    const float dxm = (float)ixn + 0.5f - kx;
    const float dym = (float)iyn + 0.5f - ky;
    const float smax = expf(-((dxm * dxm + dym * dym) / 5.12f));
    const bool  has  = valid && (smax >= 0.6f);
    const float hasf = has ? 1.0f : 0.0f;

    // ---- this thread's 4 pixels: row gy, cols gx0..gx0+3 ----
    const int gy  = tid >> 3;            // 32 rows, 8 float4 groups per row
    const int gx0 = (tid & 7) << 2;

    const float dy   = (float)gy + 0.5f - ky;
    const float offy = ky - (float)gy;
    const float dy2  = dy * dy;

    float sc[4], offx[4], m2f[4], m3f[4];
#pragma unroll
    for (int j = 0; j < 4; ++j) {
        const float gx = (float)(gx0 + j);
        const float dx = gx + 0.5f - kx;
        sc[j]   = expf(-((dx * dx + dy2) / 5.12f));
        offx[j] = kx - gx;
        const bool b2 = valid && (sc[j] >= 0.6f);
        const bool b3 = valid && (sc[j] >= 0.5f);   // == depth mask (thr 0.5)
        m2f[j] = b2 ? 1.0f : 0.0f;
        m3f[j] = b3 ? 1.0f : 0.0f;
    }

    // ---- 20 coalesced float4 streaming stores ----
    const long long pix  = (long long)tid * 4;            // gy*32 + gx0
    const long long base = (long long)bn * HW + pix;      // C=1 tensors
    const long long b2c  = (long long)bn * 2 * HW + pix;  // C=2 tensors, ch0
    const long long b3c  = (long long)bn * 3 * HW + pix;  // C=3 tensors, ch0

    // cls_label / cls_label_w
    if (has) stream4(out + OFF_CLS + base, sc[0], sc[1], sc[2], sc[3]);
    else     stream4(out + OFF_CLS + base, -1.0f, -1.0f, -1.0f, -1.0f);
    stream4(out + OFF_CLSW + base, hasf, hasf, hasf, hasf);

    // reg_2d (offx*m2, offy*m2) / reg_2d_w (m2, m2)
    stream4(out + OFF_R2  + b2c,      offx[0]*m2f[0], offx[1]*m2f[1], offx[2]*m2f[2], offx[3]*m2f[3]);
    stream4(out + OFF_R2  + b2c + HW, offy*m2f[0],    offy*m2f[1],    offy*m2f[2],    offy*m2f[3]);
    stream4(out + OFF_R2W + b2c,      m2f[0], m2f[1], m2f[2], m2f[3]);
    stream4(out + OFF_R2W + b2c + HW, m2f[0], m2f[1], m2f[2], m2f[3]);

    // reg_3d / reg_3d_w
    stream4(out + OFF_R3  + b2c,      offx[0]*m3f[0], offx[1]*m3f[1], offx[2]*m3f[2], offx[3]*m3f[3]);
    stream4(out + OFF_R3  + b2c + HW, offy*m3f[0],    offy*m3f[1],    offy*m3f[2],    offy*m3f[3]);
    stream4(out + OFF_R3W + b2c,      m3f[0], m3f[1], m3f[2], m3f[3]);
    stream4(out + OFF_R3W + b2c + HW, m3f[0], m3f[1], m3f[2], m3f[3]);

    // depth (mask thr 0.5 == m3f)
    stream4(out + OFF_DL  + base, depth*m3f[0], depth*m3f[1], depth*m3f[2], depth*m3f[3]);
    stream4(out + OFF_DLW + base, m3f[0], m3f[1], m3f[2], m3f[3]);

    // dims (3 channels) * m3f, weights = m3f
    stream4(out + OFF_DIM  + b3c,        dim0*m3f[0], dim0*m3f[1], dim0*m3f[2], dim0*m3f[3]);
    stream4(out + OFF_DIM  + b3c + HW,   dim1*m3f[0], dim1*m3f[1], dim1*m3f[2], dim1*m3f[3]);
    stream4(out + OFF_DIM  + b3c + 2*HW, dim2*m3f[0], dim2*m3f[1], dim2*m3f[2], dim2*m3f[3]);
    stream4(out + OFF_DIMW + b3c,        m3f[0], m3f[1], m3f[2], m3f[3]);
    stream4(out + OFF_DIMW + b3c + HW,   m3f[0], m3f[1], m3f[2], m3f[3]);
    stream4(out + OFF_DIMW + b3c + 2*HW, m3f[0], m3f[1], m3f[2], m3f[3]);

    // rot
    stream4(out + OFF_ROT  + base, rot*m3f[0], rot*m3f[1], rot*m3f[2], rot*m3f[3]);
    stream4(out + OFF_ROTW + base, m3f[0], m3f[1], m3f[2], m3f[3]);
}

extern "C" void kernel_launch(void* const* d_in, const int* in_sizes, int n_in,
                              void* d_out, int out_size) {
    const float* boxes          = (const float*)d_in[0];
    const float* gt_boxes       = (const float*)d_in[1];
    const int*   match_pos_flag = (const int*)d_in[2];
    const int*   match_gt_id    = (const int*)d_in[3];
    float* out = (float*)d_out;

    // One CTA per (b,n) box: 4*1024 = 4096 CTAs, 256 threads each,
    // each thread writes one float4 of every one of the 20 output channels.
    rcnn3d_label_kernel<<<4096, 256>>>(boxes, gt_boxes, match_pos_flag,
                                       match_gt_id, out);
}

// round 2
// speedup vs baseline: 1.0081x; 1.0081x over previous
#include <cuda_runtime.h>

// Problem constants (match reference)
#define FEAT_W   32
#define FEAT_H   32
#define HW       1024          // 32*32
#define N_BOX    1024          // N
#define M_GT     64            // M
#define GT_STRIDE 14

// Output tensor offsets in floats (concatenation of the 12 returned tensors)
// BN = 4*1024 = 4096 ; per-channel slab = BN*HW = 4,194,304 floats
#define SLAB     4194304ll
#define OFF_CLS   (0ll)              // cls_label      (B,N,1,H,W)
#define OFF_CLSW  (SLAB*1)           // cls_label_w    (B,N,1,H,W)
#define OFF_R2    (SLAB*2)           // reg_2d         (B,N,2,H,W)
#define OFF_R2W   (SLAB*4)           // reg_2d_w       (B,N,2,H,W)
#define OFF_R3    (SLAB*6)           // reg_3d         (B,N,2,H,W)
#define OFF_R3W   (SLAB*8)           // reg_3d_w       (B,N,2,H,W)
#define OFF_DL    (SLAB*10)          // depth_label    (B,N,1,H,W)
#define OFF_DLW   (SLAB*11)          // depth_label_w  (B,N,1,H,W)
#define OFF_DIM   (SLAB*12)          // dim_label      (B,N,3,H,W)
#define OFF_DIMW  (SLAB*15)          // dim_label_w    (B,N,3,H,W)
#define OFF_ROT   (SLAB*18)          // rot_label      (B,N,1,H,W)
#define OFF_ROTW  (SLAB*19)          // rot_label_w    (B,N,1,H,W)

__device__ __forceinline__ void stream4(float* p, float a, float b, float c, float d) {
    float4 v = make_float4(a, b, c, d);
    __stcs(reinterpret_cast<float4*>(p), v);
}

__global__ __launch_bounds__(256, 8)
void rcnn3d_label_kernel(const float* __restrict__ boxes,
                         const float* __restrict__ gt_boxes,
                         const int*   __restrict__ match_pos_flag,
                         const int*   __restrict__ match_gt_id,
                         float*       __restrict__ out)
{
    const int bn  = blockIdx.x;            // 0 .. 4095  (b*N + n)
    const int b   = bn >> 10;              // N = 1024
    const int tid = threadIdx.x;           // 0 .. 255, one float4 of pixels each

    // Separable Gaussian factors: score(gx,gy) = exs[gx] * eys[gy]
    __shared__ __align__(16) float exs[FEAT_W];
    __shared__ __align__(16) float eys[FEAT_H];

    // ---- per-box scalars (uniform across block; broadcast loads from L1) ----
    const float x1 = __ldg(boxes + (size_t)bn * 4 + 0);
    const float y1 = __ldg(boxes + (size_t)bn * 4 + 1);
    const float x2 = __ldg(boxes + (size_t)bn * 4 + 2);
    const float y2 = __ldg(boxes + (size_t)bn * 4 + 3);

    const int gid  = __ldg(match_gt_id + bn);
    const int flag = __ldg(match_pos_flag + bn);

    const float* g = gt_boxes + ((size_t)b * M_GT + gid) * GT_STRIDE;
    const float kxg   = __ldg(g + 4);
    const float kyg   = __ldg(g + 5);
    const float vis   = __ldg(g + 6);
    const float dim0  = __ldg(g + 7);
    const float dim1  = __ldg(g + 8);
    const float dim2  = __ldg(g + 9);
    const float depth = __ldg(g + 12);
    const float rot   = __ldg(g + 13);

    const float cx = 0.5f * (x1 + x2);
    const float cy = 0.5f * (y1 + y2);
    const float hw = 0.5f * (x2 - x1) * 1.2f;   // EXPAND
    const float hh = 0.5f * (y2 - y1) * 1.2f;
    const float ex1 = cx - hw, ex2 = cx + hw;
    const float ey1 = cy - hh, ey2 = cy + hh;
    const float sx = (float)FEAT_W / (ex2 - ex1 + 1.0f);
    const float sy = (float)FEAT_H / (ey2 - ey1 + 1.0f);
    const float kx = (kxg - ex1) * sx;
    const float ky = (kyg - ey1) * sy;

    const bool valid = (vis != 0.0f) && (flag > 0);

    // ---- fill separable factor tables: 64 expf per CTA (was 1024) ----
    if (tid < FEAT_W) {
        const float d = (float)tid + 0.5f - kx;
        exs[tid] = expf(-(d * d) / 5.12f);           // 2*SIGMA^2 = 5.12
    } else if (tid < FEAT_W + FEAT_H) {
        const int r = tid - FEAT_W;
        const float d = (float)r + 0.5f - ky;
        eys[r] = expf(-(d * d) / 5.12f);
    }
    __syncthreads();

    // ---- analytic 'has': max of exs[gx]*eys[gy] = exs[argmax]*eys[argmax] ----
    int ixn = __float2int_rn(kx - 0.5f); ixn = min(FEAT_W - 1, max(0, ixn));
    int iyn = __float2int_rn(ky - 0.5f); iyn = min(FEAT_H - 1, max(0, iyn));
    const float smax = exs[ixn] * eys[iyn];
    const bool  has  = valid && (smax >= 0.6f);
    const float hasf = has ? 1.0f : 0.0f;

    // ---- this thread's 4 pixels: row gy, cols gx0..gx0+3 ----
    const int gy  = tid >> 3;            // 32 rows, 8 float4 groups per row
    const int gx0 = (tid & 7) << 2;

    const float ey   = eys[gy];
    const float offy = ky - (float)gy;
    const float4 exv = reinterpret_cast<const float4*>(exs)[tid & 7];  // exs[gx0..gx0+3]

    float sc[4], offx[4], m2f[4], m3f[4];
    const float exa[4] = {exv.x, exv.y, exv.z, exv.w};
#pragma unroll
    for (int j = 0; j < 4; ++j) {
        const float gx = (float)(gx0 + j);
        sc[j]   = exa[j] * ey;                       // separable Gaussian
        offx[j] = kx - gx;
        const bool b2 = valid && (sc[j] >= 0.6f);
        const bool b3 = valid && (sc[j] >= 0.5f);    // == depth mask (thr 0.5)
        m2f[j] = b2 ? 1.0f : 0.0f;
        m3f[j] = b3 ? 1.0f : 0.0f;
    }

    // ---- 20 coalesced float4 streaming stores ----
    const long long pix  = (long long)tid * 4;            // gy*32 + gx0
    const long long base = (long long)bn * HW + pix;      // C=1 tensors
    const long long b2c  = (long long)bn * 2 * HW + pix;  // C=2 tensors, ch0
    const long long b3c  = (long long)bn * 3 * HW + pix;  // C=3 tensors, ch0

    // cls_label / cls_label_w
    if (has) stream4(out + OFF_CLS + base, sc[0], sc[1], sc[2], sc[3]);
    else     stream4(out + OFF_CLS + base, -1.0f, -1.0f, -1.0f, -1.0f);
    stream4(out + OFF_CLSW + base, hasf, hasf, hasf, hasf);

    // reg_2d (offx*m2, offy*m2) / reg_2d_w (m2, m2)
    stream4(out + OFF_R2  + b2c,      offx[0]*m2f[0], offx[1]*m2f[1], offx[2]*m2f[2], offx[3]*m2f[3]);
    stream4(out + OFF_R2  + b2c + HW, offy*m2f[0],    offy*m2f[1],    offy*m2f[2],    offy*m2f[3]);
    stream4(out + OFF_R2W + b2c,      m2f[0], m2f[1], m2f[2], m2f[3]);
    stream4(out + OFF_R2W + b2c + HW, m2f[0], m2f[1], m2f[2], m2f[3]);

    // reg_3d / reg_3d_w
    stream4(out + OFF_R3  + b2c,      offx[0]*m3f[0], offx[1]*m3f[1], offx[2]*m3f[2], offx[3]*m3f[3]);
    stream4(out + OFF_R3  + b2c + HW, offy*m3f[0],    offy*m3f[1],    offy*m3f[2],    offy*m3f[3]);
    stream4(out + OFF_R3W + b2c,      m3f[0], m3f[1], m3f[2], m3f[3]);
    stream4(out + OFF_R3W + b2c + HW, m3f[0], m3f[1], m3f[2], m3f[3]);

    // depth (mask thr 0.5 == m3f)
    stream4(out + OFF_DL  + base, depth*m3f[0], depth*m3f[1], depth*m3f[2], depth*m3f[3]);
    stream4(out + OFF_DLW + base, m3f[0], m3f[1], m3f[2], m3f[3]);

    // dims (3 channels) * m3f, weights = m3f
    stream4(out + OFF_DIM  + b3c,        dim0*m3f[0], dim0*m3f[1], dim0*m3f[2], dim0*m3f[3]);
    stream4(out + OFF_DIM  + b3c + HW,   dim1*m3f[0], dim1*m3f[1], dim1*m3f[2], dim1*m3f[3]);
    stream4(out + OFF_DIM  + b3c + 2*HW, dim2*m3f[0], dim2*m3f[1], dim2*m3f[2], dim2*m3f[3]);
    stream4(out + OFF_DIMW + b3c,        m3f[0], m3f[1], m3f[2], m3f[3]);
    stream4(out + OFF_DIMW + b3c + HW,   m3f[0], m3f[1], m3f[2], m3f[3]);
    stream4(out + OFF_DIMW + b3c + 2*HW, m3f[0], m3f[1], m3f[2], m3f[3]);

    // rot
    stream4(out + OFF_ROT  + base, rot*m3f[0], rot*m3f[1], rot*m3f[2], rot*m3f[3]);
    stream4(out + OFF_ROTW + base, m3f[0], m3f[1], m3f[2], m3f[3]);
}

extern "C" void kernel_launch(void* const* d_in, const int* in_sizes, int n_in,
                              void* d_out, int out_size) {
    const float* boxes          = (const float*)d_in[0];
    const float* gt_boxes       = (const float*)d_in[1];
    const int*   match_pos_flag = (const int*)d_in[2];
    const int*   match_gt_id    = (const int*)d_in[3];
    float* out = (float*)d_out;

    // One CTA per (b,n) box: 4*1024 = 4096 CTAs, 256 threads each,
    // each thread writes one float4 of every one of the 20 output channels.
    rcnn3d_label_kernel<<<4096, 256>>>(boxes, gt_boxes, match_pos_flag,
                                       match_gt_id, out);
}